// round 1
// baseline (speedup 1.0000x reference)
#include <cuda_runtime.h>
#include <math.h>

// ---------------- constants ----------------
#define B_ 16
#define N_ 4096
#define C_ 256
#define H_ 4
#define D_ 64
#define M_ (B_ * N_)          // 65536
#define OUT_MAIN (M_ * C_)    // 16777216
#define OUT_S (B_ * H_ * D_ * D_) // 262144

// ---------------- device scratch (no allocations allowed) ----------------
__device__ float g_q[M_ * C_];
__device__ float g_k[M_ * C_];
__device__ float g_v[M_ * C_];
__device__ float g_pred[M_ * C_];
__device__ float g_y[M_ * C_];
__device__ float g_yn[M_ * C_];
__device__ float g_beta[B_ * H_ * N_];
__device__ float g_perr[8 * B_ * H_ * D_];
__device__ float g_pkey[8 * B_ * H_ * D_];
__device__ float g_werr[B_ * H_ * D_];
__device__ float g_wkey[B_ * H_ * D_];

// ---------------- shared 128x128x8 SGEMM body ----------------
// C[M,Nc] = A[M,K] * B[Nc,K]^T  (both row-major, K contiguous). Full tiles only.
__device__ __forceinline__ void gemm128_body(
    const float* __restrict__ A, const float* __restrict__ B,
    float* __restrict__ C, int K, int ldc, int bm, int bn)
{
    __shared__ float As[8][128];
    __shared__ float Bs[8][128];
    const int tid = threadIdx.x;
    const int arow = tid >> 1;
    const int acol = (tid & 1) * 4;
    const int tx = tid & 15, ty = tid >> 4;
    const int row0 = ty * 8, col0 = tx * 8;

    float acc[8][8];
#pragma unroll
    for (int i = 0; i < 8; i++)
#pragma unroll
        for (int j = 0; j < 8; j++) acc[i][j] = 0.f;

    const float* Aptr = A + (bm + arow) * K + acol;
    const float* Bptr = B + (bn + arow) * K + acol;

    for (int k0 = 0; k0 < K; k0 += 8) {
        float4 av = *(const float4*)(Aptr + k0);
        float4 bv = *(const float4*)(Bptr + k0);
        As[acol + 0][arow] = av.x; As[acol + 1][arow] = av.y;
        As[acol + 2][arow] = av.z; As[acol + 3][arow] = av.w;
        Bs[acol + 0][arow] = bv.x; Bs[acol + 1][arow] = bv.y;
        Bs[acol + 2][arow] = bv.z; Bs[acol + 3][arow] = bv.w;
        __syncthreads();
#pragma unroll
        for (int kk = 0; kk < 8; kk++) {
            float af[8], bf[8];
            *(float4*)af       = *(const float4*)&As[kk][row0];
            *(float4*)(af + 4) = *(const float4*)&As[kk][row0 + 4];
            *(float4*)bf       = *(const float4*)&Bs[kk][col0];
            *(float4*)(bf + 4) = *(const float4*)&Bs[kk][col0 + 4];
#pragma unroll
            for (int i = 0; i < 8; i++)
#pragma unroll
                for (int j = 0; j < 8; j++)
                    acc[i][j] += af[i] * bf[j];
        }
        __syncthreads();
    }
#pragma unroll
    for (int i = 0; i < 8; i++) {
        float4 o0 = make_float4(acc[i][0], acc[i][1], acc[i][2], acc[i][3]);
        float4 o1 = make_float4(acc[i][4], acc[i][5], acc[i][6], acc[i][7]);
        float* crow = C + (bm + row0 + i) * ldc + bn + col0;
        *(float4*)crow = o0;
        *(float4*)(crow + 4) = o1;
    }
}

// ---------------- K1: fused QKV projection ----------------
__global__ void __launch_bounds__(256)
gemm_qkv_kernel(const float* __restrict__ x,
                const float* __restrict__ Wq,
                const float* __restrict__ Wk,
                const float* __restrict__ Wv)
{
    int bm = blockIdx.x * 128;
    int ct = blockIdx.y;           // 0..5
    int sel = ct >> 1;
    int bn = (ct & 1) * 128;
    const float* W = (sel == 0) ? Wq : (sel == 1) ? Wk : Wv;
    float* out = (sel == 0) ? g_q : (sel == 1) ? g_k : g_v;
    gemm128_body(x, W, out, C_, C_, bm, bn);
}

// ---------------- K2: beta = sigmoid(x @ Wb^T) ----------------
__global__ void __launch_bounds__(256)
beta_kernel(const float* __restrict__ x, const float* __restrict__ Wb)
{
    int warp = (blockIdx.x * blockDim.x + threadIdx.x) >> 5;
    int lane = threadIdx.x & 31;
    if (warp >= M_) return;
    int m = warp;
    float a0 = 0.f, a1 = 0.f, a2 = 0.f, a3 = 0.f;
    for (int c = lane; c < C_; c += 32) {
        float xv = x[m * C_ + c];
        a0 += xv * Wb[0 * C_ + c];
        a1 += xv * Wb[1 * C_ + c];
        a2 += xv * Wb[2 * C_ + c];
        a3 += xv * Wb[3 * C_ + c];
    }
#pragma unroll
    for (int o = 16; o; o >>= 1) {
        a0 += __shfl_down_sync(0xffffffffu, a0, o);
        a1 += __shfl_down_sync(0xffffffffu, a1, o);
        a2 += __shfl_down_sync(0xffffffffu, a2, o);
        a3 += __shfl_down_sync(0xffffffffu, a3, o);
    }
    if (lane == 0) {
        int b = m >> 12, n = m & (N_ - 1);
        g_beta[(b * H_ + 0) * N_ + n] = 1.f / (1.f + expf(-a0));
        g_beta[(b * H_ + 1) * N_ + n] = 1.f / (1.f + expf(-a1));
        g_beta[(b * H_ + 2) * N_ + n] = 1.f / (1.f + expf(-a2));
        g_beta[(b * H_ + 3) * N_ + n] = 1.f / (1.f + expf(-a3));
    }
}

// ---------------- K3: k = (elu(k)+1) / (||.||_2 + 1e-6), per (m,h) ----------------
__global__ void __launch_bounds__(256)
knorm_kernel()
{
    int warp = (blockIdx.x * blockDim.x + threadIdx.x) >> 5;
    int lane = threadIdx.x & 31;
    if (warp >= M_ * H_) return;
    int m = warp >> 2;
    int h = warp & 3;
    float* kp = g_k + m * C_ + h * D_;
    float a = kp[lane];
    float b = kp[lane + 32];
    a = (a > 0.f) ? (a + 1.f) : expf(a);
    b = (b > 0.f) ? (b + 1.f) : expf(b);
    float ss = a * a + b * b;
#pragma unroll
    for (int o = 16; o; o >>= 1) ss += __shfl_xor_sync(0xffffffffu, ss, o);
    float inv = 1.f / (sqrtf(ss) + 1e-6f);
    kp[lane] = a * inv;
    kp[lane + 32] = b * inv;
}

// ---------------- K4: y = q @ Sd^T, pred = k @ Sd^T, per (b,h) ----------------
// grid (B*H, N/128), dynamic smem: Sd^T (64x64) + q^T (64x128) + k^T (64x128)
__global__ void __launch_bounds__(256)
state_apply_kernel(const float* __restrict__ S)
{
    extern __shared__ float sm[];
    float* sd = sm;            // sd[j*64 + i] = 0.95 * S[bh][i][j]
    float* qs = sm + 64 * 64;  // qs[j*128 + nn]
    float* ks = qs + 64 * 128;

    int tid = threadIdx.x;
    int bh = blockIdx.x;
    int b = bh >> 2, h = bh & 3;
    int n0 = blockIdx.y * 128;

    for (int idx = tid; idx < 64 * 64; idx += 256) {
        int i = idx >> 6, j = idx & 63;
        sd[j * 64 + i] = S[bh * 4096 + idx] * 0.95f;
    }
    {
        int nn = tid >> 1;
        int j4 = (tid & 1) * 4;
        int gbase = (b * N_ + n0 + nn) * C_ + h * D_;
#pragma unroll
        for (int jb = 0; jb < 64; jb += 8) {
            float4 qv = *(const float4*)&g_q[gbase + jb + j4];
            float4 kv = *(const float4*)&g_k[gbase + jb + j4];
            qs[(jb + j4 + 0) * 128 + nn] = qv.x;
            qs[(jb + j4 + 1) * 128 + nn] = qv.y;
            qs[(jb + j4 + 2) * 128 + nn] = qv.z;
            qs[(jb + j4 + 3) * 128 + nn] = qv.w;
            ks[(jb + j4 + 0) * 128 + nn] = kv.x;
            ks[(jb + j4 + 1) * 128 + nn] = kv.y;
            ks[(jb + j4 + 2) * 128 + nn] = kv.z;
            ks[(jb + j4 + 3) * 128 + nn] = kv.w;
        }
    }
    __syncthreads();

    int tx = tid & 15, ty = tid >> 4;
    int i0 = tx * 4;
    int nb = ty * 8;
    float ay[8][4], ap[8][4];
#pragma unroll
    for (int u = 0; u < 8; u++)
#pragma unroll
        for (int v = 0; v < 4; v++) { ay[u][v] = 0.f; ap[u][v] = 0.f; }

    for (int j = 0; j < 64; j++) {
        float4 sdv = *(const float4*)&sd[j * 64 + i0];
        float qf[8], kf[8];
        *(float4*)qf       = *(const float4*)&qs[j * 128 + nb];
        *(float4*)(qf + 4) = *(const float4*)&qs[j * 128 + nb + 4];
        *(float4*)kf       = *(const float4*)&ks[j * 128 + nb];
        *(float4*)(kf + 4) = *(const float4*)&ks[j * 128 + nb + 4];
#pragma unroll
        for (int u = 0; u < 8; u++) {
            ay[u][0] += qf[u] * sdv.x; ay[u][1] += qf[u] * sdv.y;
            ay[u][2] += qf[u] * sdv.z; ay[u][3] += qf[u] * sdv.w;
            ap[u][0] += kf[u] * sdv.x; ap[u][1] += kf[u] * sdv.y;
            ap[u][2] += kf[u] * sdv.z; ap[u][3] += kf[u] * sdv.w;
        }
    }
#pragma unroll
    for (int u = 0; u < 8; u++) {
        int m = b * N_ + n0 + nb + u;
        *(float4*)&g_y[m * C_ + h * D_ + i0]    = make_float4(ay[u][0], ay[u][1], ay[u][2], ay[u][3]);
        *(float4*)&g_pred[m * C_ + h * D_ + i0] = make_float4(ap[u][0], ap[u][1], ap[u][2], ap[u][3]);
    }
}

// ---------------- K5a: partial reductions over n (deterministic) ----------------
__global__ void __launch_bounds__(256)
red_partial_kernel()
{
    int bh = blockIdx.x;        // 0..63
    int chunk = blockIdx.y;     // 0..7
    int b = bh >> 2, h = bh & 3;
    int t = threadIdx.x;
    int i = t & 63, g = t >> 6;
    float se = 0.f, sk = 0.f;
    int nend = (chunk + 1) * 512;
    for (int n = chunk * 512 + g; n < nend; n += 4) {
        int m = b * N_ + n;
        int c = h * D_ + i;
        float bv = g_beta[bh * N_ + n];
        float pv = g_pred[m * C_ + c];
        float vv = g_v[m * C_ + c];
        se += bv * (vv - pv);
        sk += g_k[m * C_ + c];
    }
    __shared__ float s1[4][64], s2[4][64];
    s1[g][i] = se; s2[g][i] = sk;
    __syncthreads();
    if (g == 0) {
        se = s1[0][i] + s1[1][i] + s1[2][i] + s1[3][i];
        sk = s2[0][i] + s2[1][i] + s2[2][i] + s2[3][i];
        g_perr[(chunk * 64 + bh) * 64 + i] = se;
        g_pkey[(chunk * 64 + bh) * 64 + i] = sk;
    }
}

// ---------------- K5b: finalize means ----------------
__global__ void __launch_bounds__(256)
red_final_kernel()
{
    int gid = blockIdx.x * 256 + threadIdx.x;   // 0..4095
    if (gid >= B_ * H_ * D_) return;
    int bh = gid >> 6, i = gid & 63;
    float se = 0.f, sk = 0.f;
#pragma unroll
    for (int c = 0; c < 8; c++) {
        se += g_perr[(c * 64 + bh) * 64 + i];
        sk += g_pkey[(c * 64 + bh) * 64 + i];
    }
    g_werr[gid] = se * (1.f / (float)N_);
    g_wkey[gid] = sk * (1.f / (float)N_);
}

// ---------------- K6: S_new ----------------
__global__ void __launch_bounds__(256)
snew_kernel(const float* __restrict__ S, float* __restrict__ out_s)
{
    int idx = blockIdx.x * 256 + threadIdx.x;
    if (idx >= OUT_S) return;
    int bh = idx >> 12;
    int i = (idx >> 6) & 63;
    int j = idx & 63;
    float val = S[idx] * 0.95f + g_werr[bh * 64 + i] * g_wkey[bh * 64 + j];
    out_s[idx] = fminf(fmaxf(val, -10.f), 10.f);
}

// ---------------- K7: RMSNorm over C ----------------
__global__ void __launch_bounds__(256)
rmsnorm_kernel(const float* __restrict__ g_rms)
{
    int m = blockIdx.x;
    int t = threadIdx.x;
    float v = g_y[m * C_ + t];
    __shared__ float red[256];
    red[t] = v * v;
    __syncthreads();
    for (int s = 128; s > 0; s >>= 1) {
        if (t < s) red[t] += red[t + s];
        __syncthreads();
    }
    float scale = rsqrtf(red[0] * (1.f / (float)C_) + 1e-6f);
    g_yn[m * C_ + t] = v * scale * g_rms[t];
}

// ---------------- K8: output projection ----------------
__global__ void __launch_bounds__(256)
gemm_out_kernel(const float* __restrict__ Wo, float* __restrict__ out)
{
    int bm = blockIdx.x * 128;
    int bn = blockIdx.y * 128;
    gemm128_body(g_yn, Wo, out, C_, C_, bm, bn);
}

// ---------------- launcher ----------------
extern "C" void kernel_launch(void* const* d_in, const int* in_sizes, int n_in,
                              void* d_out, int out_size)
{
    const float* x    = (const float*)d_in[0];
    const float* S    = (const float*)d_in[1];
    const float* Wq   = (const float*)d_in[2];
    const float* Wk   = (const float*)d_in[3];
    const float* Wv   = (const float*)d_in[4];
    const float* Wb   = (const float*)d_in[5];
    const float* Wo   = (const float*)d_in[6];
    const float* grms = (const float*)d_in[7];
    float* out = (float*)d_out;

    // K1: qkv projection  (M=65536, N=768, K=256)
    gemm_qkv_kernel<<<dim3(M_ / 128, 6), 256>>>(x, Wq, Wk, Wv);

    // K2: beta gates
    beta_kernel<<<M_ / 8, 256>>>(x, Wb);

    // K3: key feature map + L2 normalize
    knorm_kernel<<<(M_ * H_) / 8, 256>>>();

    // K4: y / pred state GEMMs (80KB dynamic smem)
    static int smem_set = 0;
    if (!smem_set) {
        cudaFuncSetAttribute(state_apply_kernel,
                             cudaFuncAttributeMaxDynamicSharedMemorySize, 81920);
        smem_set = 1;
    }
    state_apply_kernel<<<dim3(B_ * H_, N_ / 128), 256, 81920>>>(S);

    // K5: delta-rule reductions (deterministic two-stage)
    red_partial_kernel<<<dim3(B_ * H_, 8), 256>>>();
    red_final_kernel<<<16, 256>>>();

    // K6: S_new (only if the harness output includes it)
    if (out_size >= OUT_MAIN + OUT_S) {
        snew_kernel<<<OUT_S / 256, 256>>>(S, out + OUT_MAIN);
    }

    // K7: RMSNorm
    rmsnorm_kernel<<<M_, 256>>>(grms);

    // K8: output projection -> d_out
    gemm_out_kernel<<<dim3(M_ / 128, 2), 256>>>(Wo, out);
}

// round 3
// speedup vs baseline: 2.3297x; 2.3297x over previous
#include <cuda_runtime.h>
#include <cuda_bf16.h>
#include <math.h>

// ---------------- constants ----------------
#define B_ 16
#define N_ 4096
#define C_ 256
#define H_ 4
#define D_ 64
#define M_ (B_ * N_)              // 65536
#define OUT_MAIN (M_ * C_)        // 16777216
#define OUT_S (B_ * H_ * D_ * D_) // 262144

typedef unsigned int u32;
typedef unsigned long long u64;
typedef unsigned short u16;

// ---------------- device scratch ----------------
__device__ __nv_bfloat16 g_xh[M_ * C_], g_xl[M_ * C_];
__device__ __nv_bfloat16 g_qh[M_ * C_], g_ql[M_ * C_];
__device__ __nv_bfloat16 g_kh[M_ * C_], g_kl[M_ * C_];
__device__ __nv_bfloat16 g_ynh[M_ * C_], g_ynl[M_ * C_];
__device__ float g_v[M_ * C_];
__device__ float g_y[M_ * C_];
__device__ __nv_bfloat16 g_wsh[4][C_ * C_], g_wsl[4][C_ * C_]; // q,k,v,o
__device__ float g_beta[B_ * H_ * N_];
__device__ float g_perr[32 * 64 * 64], g_pkey[32 * 64 * 64];
__device__ float g_werr[64 * 64], g_wkey[64 * 64];

// ---------------- helpers ----------------
__device__ __forceinline__ u32 smem_u32(const void* p) {
    u32 a;
    asm("{ .reg .u64 t; cvta.to.shared.u64 t, %1; cvt.u32.u64 %0, t; }" : "=r"(a) : "l"(p));
    return a;
}
__device__ __forceinline__ void ldmx4(u32* r, u32 addr) {
    asm volatile("ldmatrix.sync.aligned.m8n8.x4.shared.b16 {%0,%1,%2,%3}, [%4];"
                 : "=r"(r[0]), "=r"(r[1]), "=r"(r[2]), "=r"(r[3]) : "r"(addr));
}
__device__ __forceinline__ void mma_bf16(float* d, const u32* a, u32 b0, u32 b1) {
    asm volatile("mma.sync.aligned.m16n8k16.row.col.f32.bf16.bf16.f32 "
                 "{%0,%1,%2,%3}, {%4,%5,%6,%7}, {%8,%9}, {%0,%1,%2,%3};"
                 : "+f"(d[0]), "+f"(d[1]), "+f"(d[2]), "+f"(d[3])
                 : "r"(a[0]), "r"(a[1]), "r"(a[2]), "r"(a[3]), "r"(b0), "r"(b1));
}
__device__ __forceinline__ u32 pack2(float a, float b, float& ra, float& rb) {
    __nv_bfloat16 h0 = __float2bfloat16(a), h1 = __float2bfloat16(b);
    ra = a - __bfloat162float(h0);
    rb = b - __bfloat162float(h1);
    return (u32)__bfloat16_as_ushort(h0) | ((u32)__bfloat16_as_ushort(h1) << 16);
}
__device__ __forceinline__ float eluf(float v) {
    return (v > 0.f) ? (v + 1.f) : expf(v);
}

// ---------------- K0a: x -> split bf16 + beta gates (fused) ----------------
__global__ void __launch_bounds__(256)
convx_beta_kernel(const float* __restrict__ x, const float* __restrict__ Wb)
{
    __shared__ float wb[1024];
    for (int i = threadIdx.x; i < 1024; i += 256) wb[i] = Wb[i];
    __syncthreads();
    int wid = threadIdx.x >> 5, lane = threadIdx.x & 31;
    int m = blockIdx.x * 8 + wid;
    const float4* row = (const float4*)(x + (size_t)m * C_);
    float4 fa = row[lane], fb = row[lane + 32];

    float r0, r1, d0, d1;
    u32 ha0 = pack2(fa.x, fa.y, r0, r1); u32 la0 = pack2(r0, r1, d0, d1);
    u32 ha1 = pack2(fa.z, fa.w, r0, r1); u32 la1 = pack2(r0, r1, d0, d1);
    u32 hb0 = pack2(fb.x, fb.y, r0, r1); u32 lb0 = pack2(r0, r1, d0, d1);
    u32 hb1 = pack2(fb.z, fb.w, r0, r1); u32 lb1 = pack2(r0, r1, d0, d1);
    ((uint2*)(g_xh + (size_t)m * C_))[lane]      = make_uint2(ha0, ha1);
    ((uint2*)(g_xl + (size_t)m * C_))[lane]      = make_uint2(la0, la1);
    ((uint2*)(g_xh + (size_t)m * C_))[lane + 32] = make_uint2(hb0, hb1);
    ((uint2*)(g_xl + (size_t)m * C_))[lane + 32] = make_uint2(lb0, lb1);

    int c0 = lane * 4, c1 = 128 + lane * 4;
    float s[4];
#pragma unroll
    for (int h = 0; h < 4; h++) {
        const float* w = wb + h * 256;
        s[h] = fa.x * w[c0] + fa.y * w[c0 + 1] + fa.z * w[c0 + 2] + fa.w * w[c0 + 3]
             + fb.x * w[c1] + fb.y * w[c1 + 1] + fb.z * w[c1 + 2] + fb.w * w[c1 + 3];
    }
#pragma unroll
    for (int o = 16; o; o >>= 1) {
#pragma unroll
        for (int h = 0; h < 4; h++) s[h] += __shfl_xor_sync(0xffffffffu, s[h], o);
    }
    if (lane == 0) {
        int bb = m >> 12, n = m & (N_ - 1);
#pragma unroll
        for (int h = 0; h < 4; h++)
            g_beta[(bb * H_ + h) * N_ + n] = 1.f / (1.f + expf(-s[h]));
    }
}

// ---------------- K0b: weights -> split bf16 ----------------
__global__ void __launch_bounds__(256) convw_kernel(
    const float* __restrict__ Wq, const float* __restrict__ Wk,
    const float* __restrict__ Wv, const float* __restrict__ Wo)
{
    int gid = blockIdx.x * 256 + threadIdx.x;   // < 262144
    int sel = gid >> 16, idx = gid & 65535;
    const float* W = (sel == 0) ? Wq : (sel == 1) ? Wk : (sel == 2) ? Wv : Wo;
    float v = W[idx];
    __nv_bfloat16 h = __float2bfloat16(v);
    g_wsh[sel][idx] = h;
    g_wsl[sel][idx] = __float2bfloat16(v - __bfloat162float(h));
}

// ---------------- K1/K8: mma.sync split-bf16 GEMM, 128x128 tiles, K=256 ----------------
// task 0: QKV (grid 6 x 512), task 1: out proj (grid 2 x 512)
__global__ void __launch_bounds__(256, 2)
gemm_mma_kernel(int task, float* __restrict__ fout)
{
    extern __shared__ char smem[];
    const u32 sb = smem_u32(smem);
    const int tid = threadIdx.x, wid = tid >> 5, lane = tid & 31;
    const int m0 = blockIdx.y * 128;

    int mode, n0;
    const __nv_bfloat16 *Ah, *Al, *Bh, *Bl;
    if (task == 0) {
        int wsel = blockIdx.x >> 1; mode = wsel; n0 = (blockIdx.x & 1) * 128;
        Ah = g_xh; Al = g_xl; Bh = g_wsh[wsel]; Bl = g_wsl[wsel];
    } else {
        mode = 3; n0 = blockIdx.x * 128;
        Ah = g_ynh; Al = g_ynl; Bh = g_wsh[3]; Bl = g_wsl[3];
    }

    const u32 OAH = 0, OAL = 16384, OBH = 32768, OBL = 49152;
    const int wm = wid & 3, wn = wid >> 2;
    const int rA = (lane & 7) + ((lane >> 3) & 1) * 8, cAx = (lane >> 4) & 1;
    const int rB = (lane & 7) + ((lane >> 4) & 1) * 8, cBx = (lane >> 3) & 1;

    float acc[2][8][4];
#pragma unroll
    for (int i = 0; i < 2; i++)
#pragma unroll
        for (int j = 0; j < 8; j++)
#pragma unroll
            for (int t = 0; t < 4; t++) acc[i][j][t] = 0.f;

    const int lr = tid >> 1, lh = tid & 1;
    const size_t arow = (size_t)(m0 + lr) * C_ + lh * 32;
    const size_t brow = (size_t)(n0 + lr) * C_ + lh * 32;

    for (int c = 0; c < 4; c++) {
        const uint4* pa  = (const uint4*)(Ah + arow + c * 64);
        const uint4* pal = (const uint4*)(Al + arow + c * 64);
        const uint4* pb  = (const uint4*)(Bh + brow + c * 64);
        const uint4* pbl = (const uint4*)(Bl + brow + c * 64);
        u32 sbase = (u32)lr * 128;
#pragma unroll
        for (int j = 0; j < 4; j++) {
            u32 off = sbase + (u32)(((lh * 4 + j) ^ (lr & 7)) * 16);
            *(uint4*)(smem + OAH + off) = pa[j];
            *(uint4*)(smem + OAL + off) = pal[j];
            *(uint4*)(smem + OBH + off) = pb[j];
            *(uint4*)(smem + OBL + off) = pbl[j];
        }
        __syncthreads();
#pragma unroll
        for (int ks = 0; ks < 4; ks++) {
            u32 ah[2][4], al[2][4];
#pragma unroll
            for (int mm = 0; mm < 2; mm++) {
                int r = wm * 32 + mm * 16 + rA;
                u32 byt = (u32)r * 128 + (u32)((((2 * ks + cAx) ^ (r & 7)) << 4));
                ldmx4(ah[mm], sb + OAH + byt);
                ldmx4(al[mm], sb + OAL + byt);
            }
#pragma unroll
            for (int nh = 0; nh < 4; nh++) {
                int n = wn * 64 + nh * 16 + rB;
                u32 bytB = (u32)n * 128 + (u32)((((2 * ks + cBx) ^ (n & 7)) << 4));
                u32 bhf[4], blf[4];
                ldmx4(bhf, sb + OBH + bytB);
                ldmx4(blf, sb + OBL + bytB);
#pragma unroll
                for (int mm = 0; mm < 2; mm++) {
                    mma_bf16(acc[mm][nh * 2],     ah[mm], bhf[0], bhf[1]);
                    mma_bf16(acc[mm][nh * 2 + 1], ah[mm], bhf[2], bhf[3]);
                    mma_bf16(acc[mm][nh * 2],     al[mm], bhf[0], bhf[1]);
                    mma_bf16(acc[mm][nh * 2 + 1], al[mm], bhf[2], bhf[3]);
                    mma_bf16(acc[mm][nh * 2],     ah[mm], blf[0], blf[1]);
                    mma_bf16(acc[mm][nh * 2 + 1], ah[mm], blf[2], blf[3]);
                }
            }
        }
        __syncthreads();
    }

    // ---- epilogue ----
    const int qrow = lane >> 2, qcol = (lane & 3) * 2;
    if (mode <= 1) {
        __nv_bfloat16* Dh = (mode == 0) ? g_qh : g_kh;
        __nv_bfloat16* Dl = (mode == 0) ? g_ql : g_kl;
#pragma unroll
        for (int mm = 0; mm < 2; mm++) {
            float invl = 1.f, invh = 1.f;
            if (mode == 1) {
                float ssl = 0.f, ssh = 0.f;
#pragma unroll
                for (int nf = 0; nf < 8; nf++) {
                    float e0 = eluf(acc[mm][nf][0]); acc[mm][nf][0] = e0; ssl += e0 * e0;
                    float e1 = eluf(acc[mm][nf][1]); acc[mm][nf][1] = e1; ssl += e1 * e1;
                    float e2 = eluf(acc[mm][nf][2]); acc[mm][nf][2] = e2; ssh += e2 * e2;
                    float e3 = eluf(acc[mm][nf][3]); acc[mm][nf][3] = e3; ssh += e3 * e3;
                }
                ssl += __shfl_xor_sync(0xffffffffu, ssl, 1);
                ssl += __shfl_xor_sync(0xffffffffu, ssl, 2);
                ssh += __shfl_xor_sync(0xffffffffu, ssh, 1);
                ssh += __shfl_xor_sync(0xffffffffu, ssh, 2);
                invl = 1.f / (sqrtf(ssl) + 1e-6f);
                invh = 1.f / (sqrtf(ssh) + 1e-6f);
            }
            size_t r_lo = (size_t)(m0 + wm * 32 + mm * 16 + qrow);
            size_t r_hi = r_lo + 8;
#pragma unroll
            for (int nf = 0; nf < 8; nf++) {
                int cof = n0 + wn * 64 + nf * 8 + qcol;
                float v0 = acc[mm][nf][0] * invl, v1 = acc[mm][nf][1] * invl;
                float v2 = acc[mm][nf][2] * invh, v3 = acc[mm][nf][3] * invh;
                float r0, r1, d0, d1;
                u32 h01 = pack2(v0, v1, r0, r1); u32 l01 = pack2(r0, r1, d0, d1);
                u32 h23 = pack2(v2, v3, r0, r1); u32 l23 = pack2(r0, r1, d0, d1);
                *(u32*)(Dh + r_lo * C_ + cof) = h01;
                *(u32*)(Dl + r_lo * C_ + cof) = l01;
                *(u32*)(Dh + r_hi * C_ + cof) = h23;
                *(u32*)(Dl + r_hi * C_ + cof) = l23;
            }
        }
    } else {
        float* dst = (mode == 2) ? g_v : fout;
#pragma unroll
        for (int mm = 0; mm < 2; mm++) {
            size_t r_lo = (size_t)(m0 + wm * 32 + mm * 16 + qrow);
            size_t r_hi = r_lo + 8;
#pragma unroll
            for (int nf = 0; nf < 8; nf++) {
                int cof = n0 + wn * 64 + nf * 8 + qcol;
                *(float2*)(dst + r_lo * C_ + cof) = make_float2(acc[mm][nf][0], acc[mm][nf][1]);
                *(float2*)(dst + r_hi * C_ + cof) = make_float2(acc[mm][nf][2], acc[mm][nf][3]);
            }
        }
    }
}

// ---------------- K3: state apply + fused delta-rule partials ----------------
// grid (64 bh, 32 ntiles). warps 0-3: y = q@Sd^T + k-col sums; warps 4-7: pred + se partials.
__global__ void __launch_bounds__(256, 2)
state_mma_kernel(const float* __restrict__ S)
{
    extern __shared__ char smem[];
    const u32 sb = smem_u32(smem);
    const int tid = threadIdx.x, wid = tid >> 5, lane = tid & 31;
    const int bh = blockIdx.x, b = bh >> 2, h = bh & 3, nt = blockIdx.y;
    const int m0 = b * N_ + nt * 128;

    const u32 OQH = 0, OQL = 16384, OKH = 32768, OKL = 49152;
    const u32 OSH = 65536, OSL = 73728, ORED = 81920;

    // load q/k split tiles [128 x 64]
    {
        const int lr = tid >> 1, lh = tid & 1;
        size_t gof = (size_t)(m0 + lr) * C_ + h * 64 + lh * 32;
        const uint4* pqh = (const uint4*)(g_qh + gof);
        const uint4* pql = (const uint4*)(g_ql + gof);
        const uint4* pkh = (const uint4*)(g_kh + gof);
        const uint4* pkl = (const uint4*)(g_kl + gof);
        u32 sbase = (u32)lr * 128;
#pragma unroll
        for (int j = 0; j < 4; j++) {
            u32 off = sbase + (u32)(((lh * 4 + j) ^ (lr & 7)) * 16);
            *(uint4*)(smem + OQH + off) = pqh[j];
            *(uint4*)(smem + OQL + off) = pql[j];
            *(uint4*)(smem + OKH + off) = pkh[j];
            *(uint4*)(smem + OKL + off) = pkl[j];
        }
    }
    // Sd split tile [64 x 64]
    for (int t = tid; t < 4096; t += 256) {
        int i = t >> 6, j = t & 63;
        float v = S[(size_t)bh * 4096 + t] * 0.95f;
        __nv_bfloat16 hh = __float2bfloat16(v);
        __nv_bfloat16 ll = __float2bfloat16(v - __bfloat162float(hh));
        u32 byt = (u32)i * 128 + (u32)((((j >> 3) ^ (i & 7)) << 4)) + (u32)(j & 7) * 2;
        *(__nv_bfloat16*)(smem + OSH + byt) = hh;
        *(__nv_bfloat16*)(smem + OSL + byt) = ll;
    }
    __syncthreads();

    const int wm = wid & 3;
    const bool isPred = (wid >= 4);
    const u32 AH = isPred ? OKH : OQH, AL = isPred ? OKL : OQL;
    const int rA = (lane & 7) + ((lane >> 3) & 1) * 8, cAx = (lane >> 4) & 1;
    const int rB = (lane & 7) + ((lane >> 4) & 1) * 8, cBx = (lane >> 3) & 1;

    float acc[2][8][4];
#pragma unroll
    for (int i = 0; i < 2; i++)
#pragma unroll
        for (int j = 0; j < 8; j++)
#pragma unroll
            for (int t = 0; t < 4; t++) acc[i][j][t] = 0.f;

#pragma unroll
    for (int ks = 0; ks < 4; ks++) {
        u32 ah[2][4], al[2][4];
#pragma unroll
        for (int mm = 0; mm < 2; mm++) {
            int r = wm * 32 + mm * 16 + rA;
            u32 byt = (u32)r * 128 + (u32)((((2 * ks + cAx) ^ (r & 7)) << 4));
            ldmx4(ah[mm], sb + AH + byt);
            ldmx4(al[mm], sb + AL + byt);
        }
#pragma unroll
        for (int nh = 0; nh < 4; nh++) {
            int n = nh * 16 + rB;
            u32 bytB = (u32)n * 128 + (u32)((((2 * ks + cBx) ^ (n & 7)) << 4));
            u32 bhf[4], blf[4];
            ldmx4(bhf, sb + OSH + bytB);
            ldmx4(blf, sb + OSL + bytB);
#pragma unroll
            for (int mm = 0; mm < 2; mm++) {
                mma_bf16(acc[mm][nh * 2],     ah[mm], bhf[0], bhf[1]);
                mma_bf16(acc[mm][nh * 2 + 1], ah[mm], bhf[2], bhf[3]);
                mma_bf16(acc[mm][nh * 2],     al[mm], bhf[0], bhf[1]);
                mma_bf16(acc[mm][nh * 2 + 1], al[mm], bhf[2], bhf[3]);
                mma_bf16(acc[mm][nh * 2],     ah[mm], blf[0], blf[1]);
                mma_bf16(acc[mm][nh * 2 + 1], ah[mm], blf[2], blf[3]);
            }
        }
    }

    const int qrow = lane >> 2, qcol = (lane & 3) * 2;
    if (!isPred) {
        // write y (fp32)
#pragma unroll
        for (int mm = 0; mm < 2; mm++) {
            size_t r_lo = (size_t)(m0 + wm * 32 + mm * 16 + qrow);
            size_t r_hi = r_lo + 8;
#pragma unroll
            for (int nf = 0; nf < 8; nf++) {
                int cof = h * 64 + nf * 8 + qcol;
                *(float2*)(g_y + r_lo * C_ + cof) = make_float2(acc[mm][nf][0], acc[mm][nf][1]);
                *(float2*)(g_y + r_hi * C_ + cof) = make_float2(acc[mm][nf][2], acc[mm][nf][3]);
            }
        }
        // k column sums (over all 128 rows of the tile)
        int col = wid * 16 + (lane & 15);
        int rbase = (lane >> 4) * 64;
        float sum = 0.f;
        for (int rr = 0; rr < 64; rr++) {
            int r = rbase + rr;
            u32 byt = (u32)r * 128 + (u32)((((col >> 3) ^ (r & 7)) << 4)) + (u32)(col & 7) * 2;
            sum += __bfloat162float(*(const __nv_bfloat16*)(smem + OKH + byt))
                 + __bfloat162float(*(const __nv_bfloat16*)(smem + OKL + byt));
        }
        sum += __shfl_xor_sync(0xffffffffu, sum, 16);
        if (lane < 16)
            g_pkey[((size_t)nt * 64 + bh) * 64 + wid * 16 + lane] = sum;
    } else {
        // se partials: sum over rows of beta*(v - pred)
        float sse0[8], sse1[8];
#pragma unroll
        for (int nf = 0; nf < 8; nf++) { sse0[nf] = 0.f; sse1[nf] = 0.f; }
#pragma unroll
        for (int mm = 0; mm < 2; mm++) {
            int rl = wm * 32 + mm * 16 + qrow;
            float b_lo = g_beta[bh * N_ + nt * 128 + rl];
            float b_hi = g_beta[bh * N_ + nt * 128 + rl + 8];
            size_t glo = (size_t)(m0 + rl) * C_ + h * 64;
            size_t ghi = glo + 8 * C_;
#pragma unroll
            for (int nf = 0; nf < 8; nf++) {
                int cof = nf * 8 + qcol;
                float2 vlo = *(const float2*)(g_v + glo + cof);
                float2 vhi = *(const float2*)(g_v + ghi + cof);
                sse0[nf] += b_lo * (vlo.x - acc[mm][nf][0]) + b_hi * (vhi.x - acc[mm][nf][2]);
                sse1[nf] += b_lo * (vlo.y - acc[mm][nf][1]) + b_hi * (vhi.y - acc[mm][nf][3]);
            }
        }
#pragma unroll
        for (int o = 4; o <= 16; o <<= 1) {
#pragma unroll
            for (int nf = 0; nf < 8; nf++) {
                sse0[nf] += __shfl_xor_sync(0xffffffffu, sse0[nf], o);
                sse1[nf] += __shfl_xor_sync(0xffffffffu, sse1[nf], o);
            }
        }
        if (lane < 4) {
            float* red = (float*)(smem + ORED) + (wid - 4) * 64;
#pragma unroll
            for (int nf = 0; nf < 8; nf++) {
                red[nf * 8 + lane * 2]     = sse0[nf];
                red[nf * 8 + lane * 2 + 1] = sse1[nf];
            }
        }
    }
    __syncthreads();
    if (tid < 64) {
        const float* red = (const float*)(smem + ORED);
        float se = red[tid] + red[64 + tid] + red[128 + tid] + red[192 + tid];
        g_perr[((size_t)nt * 64 + bh) * 64 + tid] = se;
    }
}

// ---------------- K5: finalize means ----------------
__global__ void __launch_bounds__(256)
red_final_kernel()
{
    int gid = blockIdx.x * 256 + threadIdx.x;   // 0..4095
    int bh = gid >> 6, i = gid & 63;
    float se = 0.f, sk = 0.f;
#pragma unroll
    for (int c = 0; c < 32; c++) {
        se += g_perr[((size_t)c * 64 + bh) * 64 + i];
        sk += g_pkey[((size_t)c * 64 + bh) * 64 + i];
    }
    g_werr[gid] = se * (1.f / (float)N_);
    g_wkey[gid] = sk * (1.f / (float)N_);
}

// ---------------- K6: S_new ----------------
__global__ void __launch_bounds__(256)
snew_kernel(const float* __restrict__ S, float* __restrict__ out_s)
{
    int idx = blockIdx.x * 256 + threadIdx.x;
    int bh = idx >> 12;
    int i = (idx >> 6) & 63;
    int j = idx & 63;
    float val = S[idx] * 0.95f + g_werr[bh * 64 + i] * g_wkey[bh * 64 + j];
    out_s[idx] = fminf(fmaxf(val, -10.f), 10.f);
}

// ---------------- K7: RMSNorm + split bf16 (one warp per row) ----------------
__global__ void __launch_bounds__(256)
rmsnorm_kernel(const float* __restrict__ grms)
{
    int wid = threadIdx.x >> 5, lane = threadIdx.x & 31;
    int m = blockIdx.x * 8 + wid;
    const float4* row = (const float4*)(g_y + (size_t)m * C_);
    float4 fa = row[lane], fb = row[lane + 32];
    float ss = fa.x * fa.x + fa.y * fa.y + fa.z * fa.z + fa.w * fa.w
             + fb.x * fb.x + fb.y * fb.y + fb.z * fb.z + fb.w * fb.w;
#pragma unroll
    for (int o = 16; o; o >>= 1) ss += __shfl_xor_sync(0xffffffffu, ss, o);
    float sc = rsqrtf(ss * (1.f / (float)C_) + 1e-6f);
    int c0 = lane * 4, c1 = 128 + lane * 4;
    float o0 = fa.x * sc * grms[c0],     o1 = fa.y * sc * grms[c0 + 1];
    float o2 = fa.z * sc * grms[c0 + 2], o3 = fa.w * sc * grms[c0 + 3];
    float o4 = fb.x * sc * grms[c1],     o5 = fb.y * sc * grms[c1 + 1];
    float o6 = fb.z * sc * grms[c1 + 2], o7 = fb.w * sc * grms[c1 + 3];
    float r0, r1, d0, d1;
    u32 h01 = pack2(o0, o1, r0, r1); u32 l01 = pack2(r0, r1, d0, d1);
    u32 h23 = pack2(o2, o3, r0, r1); u32 l23 = pack2(r0, r1, d0, d1);
    u32 h45 = pack2(o4, o5, r0, r1); u32 l45 = pack2(r0, r1, d0, d1);
    u32 h67 = pack2(o6, o7, r0, r1); u32 l67 = pack2(r0, r1, d0, d1);
    ((uint2*)(g_ynh + (size_t)m * C_))[lane]      = make_uint2(h01, h23);
    ((uint2*)(g_ynl + (size_t)m * C_))[lane]      = make_uint2(l01, l23);
    ((uint2*)(g_ynh + (size_t)m * C_))[lane + 32] = make_uint2(h45, h67);
    ((uint2*)(g_ynl + (size_t)m * C_))[lane + 32] = make_uint2(l45, l67);
}

// ---------------- launcher ----------------
extern "C" void kernel_launch(void* const* d_in, const int* in_sizes, int n_in,
                              void* d_out, int out_size)
{
    const float* x    = (const float*)d_in[0];
    const float* S    = (const float*)d_in[1];
    const float* Wq   = (const float*)d_in[2];
    const float* Wk   = (const float*)d_in[3];
    const float* Wv   = (const float*)d_in[4];
    const float* Wb   = (const float*)d_in[5];
    const float* Wo   = (const float*)d_in[6];
    const float* grms = (const float*)d_in[7];
    float* out = (float*)d_out;

    static int init = 0;
    if (!init) {
        cudaFuncSetAttribute(gemm_mma_kernel, cudaFuncAttributeMaxDynamicSharedMemorySize, 65536);
        cudaFuncSetAttribute(state_mma_kernel, cudaFuncAttributeMaxDynamicSharedMemorySize, 82944);
        init = 1;
    }

    // x splits + beta gates (fused)
    convx_beta_kernel<<<M_ / 8, 256>>>(x, Wb);
    convw_kernel<<<1024, 256>>>(Wq, Wk, Wv, Wo);

    // QKV projection (q/k split-stores with fused elu+L2norm for k, v fp32)
    gemm_mma_kernel<<<dim3(6, 512), 256, 65536>>>(0, nullptr);

    // state apply: y + fused delta-rule partials (se, sk)
    state_mma_kernel<<<dim3(64, 32), 256, 82944>>>(S);

    // finalize means, S_new
    red_final_kernel<<<16, 256>>>();
    if (out_size >= OUT_MAIN + OUT_S) {
        snew_kernel<<<OUT_S / 256, 256>>>(S, out + OUT_MAIN);
    }

    // RMSNorm -> split bf16
    rmsnorm_kernel<<<M_ / 8, 256>>>(grms);

    // output projection -> d_out
    gemm_mma_kernel<<<dim3(2, 512), 256, 65536>>>(1, out);
}